// round 2
// baseline (speedup 1.0000x reference)
#include <cuda_runtime.h>
#include <cuda_bf16.h>
#include <cstdint>

// Problem constants: N_NODES=50000, N_EDGES=640000, D=128, OUT=1
#define MAX_NODES 50000
#define D 128

// Scratch (no cudaMalloc allowed)
__device__ float d_s1[MAX_NODES];
__device__ float d_s2[MAX_NODES];
__device__ int   d_is64;   // 1 if edge_index is int64, 0 if int32

// Detect edge_index dtype: if int64 (non-negative small values), every odd
// int32 word is 0. Sample 64 words from both halves of the array.
__global__ void detect_dtype_kernel(const int* __restrict__ ei32, int n_words) {
    int is64 = 1;
    // sample odd words spread across the buffer
    for (int i = 0; i < 64; i++) {
        long long pos = 1 + (long long)i * (n_words / 64);
        pos |= 1;  // force odd
        if (pos < n_words && ei32[pos] != 0) { is64 = 0; break; }
    }
    d_is64 = is64;
}

// Kernel 1: s1[n] = dot(X[n], W1), s2[n] = dot(X[n], W2). One warp per node.
__global__ void node_proj_kernel(const float* __restrict__ X,
                                 const float* __restrict__ W1,
                                 const float* __restrict__ W2,
                                 int n_nodes) {
    __shared__ __align__(16) float sW1[D];
    __shared__ __align__(16) float sW2[D];
    int tid = threadIdx.x;
    if (tid < D) {
        sW1[tid] = W1[tid];
        sW2[tid] = W2[tid];
    }
    __syncthreads();

    int gwarp = (blockIdx.x * blockDim.x + tid) >> 5;
    int lane = tid & 31;
    if (gwarp >= n_nodes) return;

    const float4 x  = reinterpret_cast<const float4*>(X + (size_t)gwarp * D)[lane];
    const float4 w1 = reinterpret_cast<const float4*>(sW1)[lane];
    const float4 w2 = reinterpret_cast<const float4*>(sW2)[lane];

    float a = x.x * w1.x + x.y * w1.y + x.z * w1.z + x.w * w1.w;
    float b = x.x * w2.x + x.y * w2.y + x.z * w2.z + x.w * w2.w;

    #pragma unroll
    for (int off = 16; off > 0; off >>= 1) {
        a += __shfl_xor_sync(0xFFFFFFFF, a, off);
        b += __shfl_xor_sync(0xFFFFFFFF, b, off);
    }

    if (lane == 0) {
        d_s1[gwarp] = a;
        d_s2[gwarp] = b;
    }
}

// Kernel 2: out[e] = s1[src[e]] + s2[dst[e]]. Handles int32 or int64 indices.
__global__ void edge_kernel(const void* __restrict__ ei_raw,
                            float* __restrict__ out,
                            int n_edges) {
    int e = blockIdx.x * blockDim.x + threadIdx.x;
    if (e >= n_edges) return;

    int s, d;
    if (d_is64) {
        const long long* ei = (const long long*)ei_raw;
        s = (int)ei[e];
        d = (int)ei[(size_t)n_edges + e];
    } else {
        const int* ei = (const int*)ei_raw;
        s = ei[e];
        d = ei[n_edges + e];
    }
    // Clamp defensively: a wrong dtype guess becomes a rel_err failure, not a crash.
    s = min(max(s, 0), MAX_NODES - 1);
    d = min(max(d, 0), MAX_NODES - 1);
    out[e] = d_s1[s] + d_s2[d];
}

extern "C" void kernel_launch(void* const* d_in, const int* in_sizes, int n_in,
                              void* d_out, int out_size) {
    const float* X  = (const float*)d_in[0];
    const void*  ei = d_in[1];                 // [2, E] indices, dtype detected
    const float* W1 = (const float*)d_in[2];
    const float* W2 = (const float*)d_in[3];
    float* out = (float*)d_out;

    int n_nodes = in_sizes[0] / D;             // 50000
    int n_edges = in_sizes[1] / 2;             // 640000

    // Detect dtype: if int64, int32-word count is 4*n_edges; sampling only needs
    // a lower bound, so use 2*n_edges words (valid for both layouts).
    detect_dtype_kernel<<<1, 1>>>((const int*)ei, 2 * n_edges);

    int threads1 = 256;
    int blocks1 = (n_nodes * 32 + threads1 - 1) / threads1;
    node_proj_kernel<<<blocks1, threads1>>>(X, W1, W2, n_nodes);

    int threads2 = 256;
    int blocks2 = (n_edges + threads2 - 1) / threads2;
    edge_kernel<<<blocks2, threads2>>>(ei, out, n_edges);
}

// round 3
// speedup vs baseline: 1.1236x; 1.1236x over previous
#include <cuda_runtime.h>
#include <cuda_bf16.h>
#include <cstdint>

// Problem constants: N_NODES=50000, N_EDGES=640000, D=128, OUT=1
#define MAX_NODES 50000
#define D 128

// Scratch (no cudaMalloc allowed)
__device__ float d_s1[MAX_NODES];
__device__ float d_s2[MAX_NODES];

// Kernel 1: s1[n] = dot(X[n], W1), s2[n] = dot(X[n], W2). One warp per node.
__global__ void node_proj_kernel(const float* __restrict__ X,
                                 const float* __restrict__ W1,
                                 const float* __restrict__ W2,
                                 int n_nodes) {
    __shared__ __align__(16) float sW1[D];
    __shared__ __align__(16) float sW2[D];
    int tid = threadIdx.x;
    if (tid < D) {
        sW1[tid] = W1[tid];
        sW2[tid] = W2[tid];
    }
    __syncthreads();

    int gwarp = (blockIdx.x * blockDim.x + tid) >> 5;
    int lane = tid & 31;
    if (gwarp >= n_nodes) return;

    const float4 x  = reinterpret_cast<const float4*>(X + (size_t)gwarp * D)[lane];
    const float4 w1 = reinterpret_cast<const float4*>(sW1)[lane];
    const float4 w2 = reinterpret_cast<const float4*>(sW2)[lane];

    float a = x.x * w1.x + x.y * w1.y + x.z * w1.z + x.w * w1.w;
    float b = x.x * w2.x + x.y * w2.y + x.z * w2.z + x.w * w2.w;

    #pragma unroll
    for (int off = 16; off > 0; off >>= 1) {
        a += __shfl_xor_sync(0xFFFFFFFF, a, off);
        b += __shfl_xor_sync(0xFFFFFFFF, b, off);
    }

    if (lane == 0) {
        d_s1[gwarp] = a;
        d_s2[gwarp] = b;
    }
}

// Kernel 2: out[e] = s1[src[e]] + s2[dst[e]], int32 indices, 4 edges per thread.
__global__ void edge_kernel4(const int* __restrict__ ei,
                             float* __restrict__ out,
                             int n_edges) {
    int q = blockIdx.x * blockDim.x + threadIdx.x;    // quad index
    int e0 = q * 4;
    if (e0 + 3 < n_edges) {
        int4 s4 = *reinterpret_cast<const int4*>(ei + e0);
        int4 d4 = *reinterpret_cast<const int4*>(ei + n_edges + e0);
        float4 r;
        r.x = d_s1[min(max(s4.x, 0), MAX_NODES - 1)] + d_s2[min(max(d4.x, 0), MAX_NODES - 1)];
        r.y = d_s1[min(max(s4.y, 0), MAX_NODES - 1)] + d_s2[min(max(d4.y, 0), MAX_NODES - 1)];
        r.z = d_s1[min(max(s4.z, 0), MAX_NODES - 1)] + d_s2[min(max(d4.z, 0), MAX_NODES - 1)];
        r.w = d_s1[min(max(s4.w, 0), MAX_NODES - 1)] + d_s2[min(max(d4.w, 0), MAX_NODES - 1)];
        *reinterpret_cast<float4*>(out + e0) = r;
    } else {
        for (int e = e0; e < n_edges; e++) {
            int s = min(max(ei[e], 0), MAX_NODES - 1);
            int d = min(max(ei[n_edges + e], 0), MAX_NODES - 1);
            out[e] = d_s1[s] + d_s2[d];
        }
    }
}

extern "C" void kernel_launch(void* const* d_in, const int* in_sizes, int n_in,
                              void* d_out, int out_size) {
    const float* X  = (const float*)d_in[0];
    const int*   ei = (const int*)d_in[1];     // [2, E] int32 (verified: int64 read crashed)
    const float* W1 = (const float*)d_in[2];
    const float* W2 = (const float*)d_in[3];
    float* out = (float*)d_out;

    int n_nodes = in_sizes[0] / D;             // 50000
    int n_edges = in_sizes[1] / 2;             // 640000

    // Kernel 1: one warp per node, 256 threads/block
    int threads1 = 256;
    int blocks1 = (n_nodes * 32 + threads1 - 1) / threads1;
    node_proj_kernel<<<blocks1, threads1>>>(X, W1, W2, n_nodes);

    // Kernel 2: 4 edges per thread
    int threads2 = 256;
    int quads = (n_edges + 3) / 4;
    int blocks2 = (quads + threads2 - 1) / threads2;
    edge_kernel4<<<blocks2, threads2>>>(ei, out, n_edges);
}